// round 16
// baseline (speedup 1.0000x reference)
#include <cuda_runtime.h>
#include <cuda_fp16.h>
#include <cstdint>

// Problem dims (fixed by reference)
#define BB 8
#define TT 2048
#define CC 1024
#define DD 64
#define ROWS (BB*TT)      // 16384
#define S_SPLIT 4
#define NEG_BIG  (-1.0e30f)
#define MASK_S   (-3.0e38f)
#define QSCALE   0.18033688f   // 0.125 * log2(e)

#define NTOT 192          // fused proj cols: 64 K | 64 Q | 64 V
#define KC 64             // K-chunk per pipeline stage (fp16 elems)
#define NCHUNK (CC/KC)    // 16

// proj smem: rows of 64 fp16 = 128B + 16B pad -> 144B pitch; 3-stage ring
#define PPITCH 144
#define PM 64                             // rows per proj CTA
#define XH_BYTES (PM*PPITCH)              // 9216
#define WH_BYTES (NTOT*PPITCH)            // 27648
#define STAGE_BYTES (XH_BYTES + WH_BYTES)     // 36864 (x single, w single)
#define SMEM_PROJ (3*STAGE_BYTES)             // 110592 -> 2 CTAs/SM

// attn smem: 4-stage KV ring (prefetch distance 3)
#define APITCH 144
#define Q_BYTES (128*APITCH)        // 18432 (Q single fp16)
#define KV_ARR  (64*APITCH)         // 9216
#define KV_STAGE (2*KV_ARR)         // 18432 (K, V single fp16)
#define SMEM_ATT (Q_BYTES + 4*KV_STAGE)   // 92160 -> 2 CTAs/SM

// Scratch (allocation-free: __device__ globals)
__device__ uint32_t g_po16[S_SPLIT*ROWS*32];   // partial O as f16x2 pairs
__device__ float g_pml[ROWS*8];     // [row][0..3]=m per split, [4..7]=l
__device__ __half g_wth[NTOT*CC];           // W^T fp16 single, [n][k]
__device__ __half g_qh[ROWS*DD];            // Q fp16 (pre-scaled QSCALE)
__device__ __half g_kh[ROWS*DD];            // K fp16
__device__ __half g_vh[ROWS*DD];            // V fp16 single

__device__ __forceinline__ void cpasync16u(uint32_t sa, const void* g){
  asm volatile("cp.async.cg.shared.global [%0], [%1], 16;\n" :: "r"(sa), "l"(g) : "memory");
}
__device__ __forceinline__ void cp_commit(){ asm volatile("cp.async.commit_group;\n" ::: "memory"); }
__device__ __forceinline__ void cp_wait1(){ asm volatile("cp.async.wait_group 1;\n" ::: "memory"); }
__device__ __forceinline__ void cp_wait2(){ asm volatile("cp.async.wait_group 2;\n" ::: "memory"); }

__device__ __forceinline__ uint32_t smem_u32(const void* p){
  return (uint32_t)__cvta_generic_to_shared(p);
}
__device__ __forceinline__ void ldm4(uint32_t* r, uint32_t addr){
  asm volatile("ldmatrix.sync.aligned.m8n8.x4.shared.b16 {%0,%1,%2,%3},[%4];"
    : "=r"(r[0]), "=r"(r[1]), "=r"(r[2]), "=r"(r[3]) : "r"(addr));
}
__device__ __forceinline__ void ldm4t(uint32_t* r, uint32_t addr){
  asm volatile("ldmatrix.sync.aligned.m8n8.x4.trans.shared.b16 {%0,%1,%2,%3},[%4];"
    : "=r"(r[0]), "=r"(r[1]), "=r"(r[2]), "=r"(r[3]) : "r"(addr));
}
// fp16 mma: m16n8k16, f32 accum
__device__ __forceinline__ void mma16816h(float* d, const uint32_t* a,
                                          uint32_t b0, uint32_t b1){
  asm volatile("mma.sync.aligned.m16n8k16.row.col.f32.f16.f16.f32 "
    "{%0,%1,%2,%3},{%4,%5,%6,%7},{%8,%9},{%0,%1,%2,%3};"
    : "+f"(d[0]), "+f"(d[1]), "+f"(d[2]), "+f"(d[3])
    : "r"(a[0]), "r"(a[1]), "r"(a[2]), "r"(a[3]), "r"(b0), "r"(b1));
}
// pack (a -> low half, b -> high half) as f16x2
__device__ __forceinline__ uint32_t f16pack2(float a, float b){
  uint32_t r; asm("cvt.rn.f16x2.f32 %0, %1, %2;" : "=r"(r) : "f"(b), "f"(a));
  return r;
}
__device__ __forceinline__ void f16unpack2(uint32_t u, float &a, float &b){
  asm("{ .reg .f16 l_, h_;\n\t mov.b32 {l_, h_}, %2;\n\t"
      "cvt.f32.f16 %0, l_;\n\t cvt.f32.f16 %1, h_;\n\t }"
      : "=f"(a), "=f"(b) : "r"(u));
}
// raw 2^x (MUFU.EX2)
__device__ __forceinline__ float ex2(float x){
  float y; asm("ex2.approx.f32 %0, %1;" : "=f"(y) : "f"(x)); return y;
}

// ---------------------------------------------------------------------------
// Kernel 0: W -> fp16 single, transposed [n][k], via smem tile (coalesced
// reads AND writes). grid = (CC/64, 3), 256 threads.
// ---------------------------------------------------------------------------
__global__ __launch_bounds__(256) void prep_w(
    const float* __restrict__ Wk, const float* __restrict__ Wq,
    const float* __restrict__ Wv)
{
  __shared__ float tile[64][65];
  const int kc = blockIdx.x;          // k-chunk of 64
  const int wy = blockIdx.y;          // which W
  const float* W = (wy == 0) ? Wk : ((wy == 1) ? Wq : Wv);
  const int tid = threadIdx.x;
  const int k0 = kc * 64;

  // load 64 k-rows x 64 cols, coalesced (col = fast index)
  #pragma unroll
  for (int i = 0; i < 16; i++) {
    int e = i * 256 + tid;            // 0..4095
    int k = e >> 6, c = e & 63;
    tile[k][c] = W[(size_t)(k0 + k) * DD + c];
  }
  __syncthreads();

  // write transposed: n-row gets 64 contiguous k values (as 32 u32 pairs)
  __half* outb = g_wth + (size_t)wy * 64 * CC;
  #pragma unroll
  for (int i = 0; i < 8; i++) {
    int e = i * 256 + tid;            // 0..2047
    int n = e >> 5, kp = (e & 31) * 2;
    uint32_t u = f16pack2(tile[kp][n], tile[kp + 1][n]);
    *(uint32_t*)(outb + (size_t)n * CC + k0 + kp) = u;
  }
}

// ---------------------------------------------------------------------------
// Kernel 1: QKV projection, fp16 1-term. grid = 256 CTAs x 64 rows,
// 256 thr (8 warps), warp tile 16x96, KC=64. 3-stage ring, W prefetch
// distance 2. Epilogue: Q (x QSCALE) / K / V all single fp16.
// ---------------------------------------------------------------------------
extern __shared__ char dsmem[];

__global__ __launch_bounds__(256, 2) void proj_mma(const float* __restrict__ x)
{
  const int tid  = threadIdx.x;
  const int wid  = tid >> 5;
  const int lane = tid & 31;
  const int rowBase = blockIdx.x * PM;

  const uint32_t sbase = smem_u32(dsmem);
  auto xB = [&](int st){ return sbase + (uint32_t)st * STAGE_BYTES; };
  auto wB = [&](int st){ return xB(st) + XH_BYTES; };

  const int wm = (wid & 3) * 16;       // 4 row groups x 16
  const int wn = (wid >> 2) * 96;      // 2 col groups x 96

  const uint32_t aOff = (uint32_t)((wm + (lane & 15)) * PPITCH + (lane >> 4) * 16);
  const int bN = wn + ((lane >> 4) & 1) * 8 + (lane & 7);
  const uint32_t bOff = (uint32_t)(bN * PPITCH + ((lane >> 3) & 1) * 16);

  float d[12][4];
  #pragma unroll
  for (int nf = 0; nf < 12; nf++)
    #pragma unroll
    for (int c = 0; c < 4; c++) d[nf][c] = 0.f;

  // x chunk: 64 rows x 64 cols fp32 = 1024 float4 -> 4/thread
  float4 xr[4];
  auto loadX = [&](int chunk) {
    const int k0 = chunk * KC;
    #pragma unroll
    for (int i = 0; i < 4; i++) {
      int f = i * 256 + tid;            // 0..1023
      int row = f >> 4, c4 = (f & 15) * 4;
      xr[i] = *(const float4*)(x + (size_t)(rowBase + row) * CC + k0 + c4);
    }
  };
  auto convertX = [&](int st) {
    const uint32_t xh = xB(st);
    #pragma unroll
    for (int i = 0; i < 4; i++) {
      int f = i * 256 + tid;
      int row = f >> 4;
      uint32_t boff = (uint32_t)(row * PPITCH + (f & 15) * 8);
      float4 v = xr[i];
      uint32_t h01 = f16pack2(v.x, v.y);
      uint32_t h23 = f16pack2(v.z, v.w);
      asm volatile("st.shared.v2.b32 [%0], {%1,%2};" :: "r"(xh + boff), "r"(h01), "r"(h23) : "memory");
    }
  };
  // issueW always commits (empty group when !valid) to keep group counting
  // uniform for wait_group N.
  auto issueW = [&](int chunk, bool valid) {
    if (valid) {
      const int k0 = chunk * KC;
      const uint32_t wb = wB(chunk % 3);
      #pragma unroll
      for (int i = 0; i < 6; i++) {
        int gid = i * 256 + tid;             // 0..1535
        int n = gid >> 3, c = gid & 7;
        cpasync16u(wb + (uint32_t)(n * PPITCH + c * 16),
                   g_wth + (size_t)n * CC + k0 + c * 8);
      }
    }
    cp_commit();
  };

  // ---- prologue: W groups for chunks 0,1; x0 converted; x1 in regs ----
  loadX(0);
  issueW(0, true);
  convertX(0);
  loadX(1);
  issueW(1, true);

  for (int it = 0; it < NCHUNK; it++) {
    const int cur = it % 3;
    cp_wait1();                    // W(it) ready (issued 2 iterations back)
    __syncthreads();
    issueW(it + 2, it + 2 < NCHUNK);

    #pragma unroll
    for (int ks = 0; ks < 4; ks++) {
      uint32_t ah[4];
      ldm4(ah, xB(cur) + aOff + (uint32_t)(ks * 32));
      #pragma unroll
      for (int nf2 = 0; nf2 < 6; nf2++) {
        uint32_t bw[4];
        ldm4(bw, wB(cur) + bOff + (uint32_t)(nf2 * 16 * PPITCH + ks * 32));
        mma16816h(d[2 * nf2],     ah, bw[0], bw[1]);
        mma16816h(d[2 * nf2 + 1], ah, bw[2], bw[3]);
      }
    }

    if (it + 1 < NCHUNK) convertX((it + 1) % 3);  // xr holds chunk it+1
    if (it + 2 < NCHUNK) loadX(it + 2);
  }

  // epilogue: Q single (x QSCALE), K single, V single
  const int erow = lane >> 2;
  const int ecol = (lane & 3) * 2;
  #pragma unroll
  for (int nf = 0; nf < 12; nf++) {
    int n0 = wn + nf * 8;
    int part = n0 >> 6;
    __half* hp = (part == 0) ? g_kh : ((part == 1) ? g_qh : g_vh);
    float sc = (part == 1) ? QSCALE : 1.0f;
    int col = (n0 & 63) + ecol;
    size_t r0 = (size_t)(rowBase + wm + erow);
    size_t r1 = r0 + 8;
    *(uint32_t*)(hp + r0 * DD + col) = f16pack2(d[nf][0] * sc, d[nf][1] * sc);
    *(uint32_t*)(hp + r1 * DD + col) = f16pack2(d[nf][2] * sc, d[nf][3] * sc);
  }
}

// ---------------------------------------------------------------------------
// Kernel 2: FlashAttention-2 on fp16 mma.sync. 256 thr, 8 warps (m16 each),
// 128-query blocks, heavy-first. 4-stage KV ring, prefetch distance 3.
// Softmax in base-2 (ex2.approx). Partial O stored f16x2, m/l interleaved.
// ---------------------------------------------------------------------------
__global__ __launch_bounds__(256, 2) void attn_mma()
{
  const int qb  = (TT / 128 - 1) - blockIdx.x;   // heavy-first
  const int b   = blockIdx.y;
  const int sp  = blockIdx.z;
  const int tid = threadIdx.x;
  const int wid = tid >> 5;
  const int lane = tid & 31;

  const int ntt = 2 * (qb + 1);        // total 64-key tiles for this q-block
  const int nt  = (ntt > sp) ? (ntt - sp + 3) / 4 : 0;

  float o[8][4];
  #pragma unroll
  for (int nf = 0; nf < 8; nf++)
    #pragma unroll
    for (int c = 0; c < 4; c++) o[nf][c] = 0.f;
  float m0 = NEG_BIG, m1 = NEG_BIG, l0 = 0.f, l1 = 0.f;

  const int erow = lane >> 2;
  const int ecol = (lane & 3) * 2;
  const int row0g = b * TT + qb * 128 + wid * 16 + erow;

  if (nt == 0) goto epilogue;

  {
    const uint32_t sb  = smem_u32(dsmem);
    const uint32_t QS  = sb;
    const uint32_t KVB = sb + Q_BYTES;

    auto issueKV = [&](int tix, bool valid) {
      if (valid) {
        const int k0 = (sp + tix * 4) * 64;
        const uint32_t base = KVB + (uint32_t)(tix & 3) * KV_STAGE;
        #pragma unroll
        for (int i = 0; i < 4; i++) {
          int gid = i * 256 + tid;               // 0..1023
          int arr = gid >> 9;                    // 0=K,1=V
          int g2 = gid & 511;
          int row = g2 >> 3, ch = g2 & 7;
          const __half* ap = (arr == 0) ? g_kh : g_vh;
          cpasync16u(base + (uint32_t)(arr * KV_ARR + row * APITCH + ch * 16),
                     ap + (size_t)(b * TT + k0 + row) * DD + ch * 8);
        }
      }
      cp_commit();
    };

    // ---- stage Q (group 0) + first three KV tiles (groups 1,2,3) ----
    {
      const int rbase = b * TT + qb * 128;
      #pragma unroll
      for (int i = 0; i < 4; i++) {
        int gid = i * 256 + tid;               // 0..1023
        int row = gid >> 3, ch = gid & 7;
        cpasync16u(QS + (uint32_t)(row * APITCH + ch * 16),
                   g_qh + (size_t)(rbase + row) * DD + ch * 8);
      }
      cp_commit();
    }
    issueKV(0, true);
    issueKV(1, 1 < nt);
    issueKV(2, 2 < nt);

    cp_wait2();              // Q + tile0 done (tiles 1,2 may be outstanding)
    __syncthreads();

    // ---- Q fragments (register-resident, single) ----
    const uint32_t qoff = (uint32_t)((wid * 16 + (lane & 15)) * APITCH + (lane >> 4) * 16);
    uint32_t qh[4][4];
    #pragma unroll
    for (int ks = 0; ks < 4; ks++) ldm4(qh[ks], QS + qoff + ks * 32);

    const uint32_t koff = (uint32_t)((((lane >> 4) & 1) * 8 + (lane & 7)) * APITCH + ((lane >> 3) & 1) * 16);
    const uint32_t voff = (uint32_t)((((lane >> 3) & 1) * 8 + (lane & 7)) * APITCH + ((lane >> 4) & 1) * 16);

    for (int tix = 0; tix < nt; tix++) {
      const int k0 = (sp + tix * 4) * 64;
      cp_wait2();            // tile tix ready (issued 3 iterations ago)
      __syncthreads();
      issueKV(tix + 3, tix + 3 < nt);

      const uint32_t stage = KVB + (uint32_t)(tix & 3) * KV_STAGE;
      const uint32_t KH = stage;
      const uint32_t VH = stage + KV_ARR;

      // ---- S = Q K^T (1 term) ----
      float s[8][4];
      #pragma unroll
      for (int nf = 0; nf < 8; nf++)
        #pragma unroll
        for (int c = 0; c < 4; c++) s[nf][c] = 0.f;

      #pragma unroll
      for (int ks = 0; ks < 4; ks++) {
        #pragma unroll
        for (int g = 0; g < 4; g++) {
          uint32_t bh[4];
          ldm4(bh, KH + koff + (uint32_t)(g * 16 * APITCH + ks * 32));
          mma16816h(s[2*g],   qh[ks], bh[0], bh[1]);
          mma16816h(s[2*g+1], qh[ks], bh[2], bh[3]);
        }
      }

      // ---- causal mask (diagonal tiles only) ----
      if (k0 + 63 > qb * 128) {
        const int rlo = qb * 128 + wid * 16 + erow;
        #pragma unroll
        for (int nf = 0; nf < 8; nf++) {
          int key = k0 + nf * 8 + ecol;
          if (key     > rlo)     s[nf][0] = MASK_S;
          if (key + 1 > rlo)     s[nf][1] = MASK_S;
          if (key     > rlo + 8) s[nf][2] = MASK_S;
          if (key + 1 > rlo + 8) s[nf][3] = MASK_S;
        }
      }

      // ---- online softmax, base-2 (rows: l/4 and l/4+8) ----
      float r0 = fmaxf(s[0][0], s[0][1]);
      float r1 = fmaxf(s[0][2], s[0][3]);
      #pragma unroll
      for (int nf = 1; nf < 8; nf++) {
        r0 = fmaxf(r0, fmaxf(s[nf][0], s[nf][1]));
        r1 = fmaxf(r1, fmaxf(s[nf][2], s[nf][3]));
      }
      r0 = fmaxf(r0, __shfl_xor_sync(0xffffffffu, r0, 1));
      r0 = fmaxf(r0, __shfl_xor_sync(0xffffffffu, r0, 2));
      r1 = fmaxf(r1, __shfl_xor_sync(0xffffffffu, r1, 1));
      r1 = fmaxf(r1, __shfl_xor_sync(0xffffffffu, r1, 2));
      float mn0 = fmaxf(m0, r0), mn1 = fmaxf(m1, r1);
      float cr0 = ex2(m0 - mn0), cr1 = ex2(m1 - mn1);
      l0 *= cr0; l1 *= cr1; m0 = mn0; m1 = mn1;
      #pragma unroll
      for (int nf = 0; nf < 8; nf++) {
        o[nf][0] *= cr0; o[nf][1] *= cr0;
        o[nf][2] *= cr1; o[nf][3] *= cr1;
      }

      // ---- ex2, row sums, P -> A-frag fp16 single ----
      float sum0 = 0.f, sum1 = 0.f;
      uint32_t ph[4][4];
      #pragma unroll
      for (int nf = 0; nf < 8; nf++) {
        float p0 = ex2(s[nf][0] - m0);
        float p1 = ex2(s[nf][1] - m0);
        float p2 = ex2(s[nf][2] - m1);
        float p3 = ex2(s[nf][3] - m1);
        sum0 += p0 + p1; sum1 += p2 + p3;
        int kk = nf >> 1, bs = (nf & 1) * 2;
        ph[kk][bs]     = f16pack2(p0, p1);
        ph[kk][bs + 1] = f16pack2(p2, p3);
      }
      sum0 += __shfl_xor_sync(0xffffffffu, sum0, 1);
      sum0 += __shfl_xor_sync(0xffffffffu, sum0, 2);
      sum1 += __shfl_xor_sync(0xffffffffu, sum1, 1);
      sum1 += __shfl_xor_sync(0xffffffffu, sum1, 2);
      l0 += sum0; l1 += sum1;

      // ---- O += P V (1 term; V via trans-ldmatrix) ----
      #pragma unroll
      for (int kk = 0; kk < 4; kk++) {
        #pragma unroll
        for (int dg = 0; dg < 4; dg++) {
          uint32_t vh[4];
          ldm4t(vh, VH + voff + (uint32_t)(kk * 16 * APITCH + dg * 32));
          mma16816h(o[2*dg],   ph[kk], vh[0], vh[1]);
          mma16816h(o[2*dg+1], ph[kk], vh[2], vh[3]);
        }
      }
    }
  }

epilogue:
  {
    size_t pr0 = (size_t)sp * ROWS + row0g;
    size_t pr1 = pr0 + 8;
    if ((lane & 3) == 0) {
      g_pml[(size_t)row0g * 8 + sp]           = m0;
      g_pml[(size_t)row0g * 8 + 4 + sp]       = l0;
      g_pml[(size_t)(row0g + 8) * 8 + sp]     = m1;
      g_pml[(size_t)(row0g + 8) * 8 + 4 + sp] = l1;
    }
    const int pcol = (lane & 3);
    #pragma unroll
    for (int nf = 0; nf < 8; nf++) {
      g_po16[pr0 * 32 + nf * 4 + pcol] = f16pack2(o[nf][0], o[nf][1]);
      g_po16[pr1 * 32 + nf * 4 + pcol] = f16pack2(o[nf][2], o[nf][3]);
    }
  }
}

// ---------------------------------------------------------------------------
// Kernel 3: LSE combine (base-2 weights). One thread per output float4,
// grid = 1024 x 256. m/l loaded as 2x LDG.128 from interleaved g_pml.
// ---------------------------------------------------------------------------
__global__ __launch_bounds__(256) void combine_kernel(float* __restrict__ out)
{
  int gid = blockIdx.x * 256 + threadIdx.x;   // 0 .. ROWS*16-1
  int r  = gid >> 4;
  int pc = (gid & 15) * 2;                    // f16x2-pair index (0..30)

  float4 m4 = *(const float4*)&g_pml[(size_t)r * 8];
  float4 l4 = *(const float4*)&g_pml[(size_t)r * 8 + 4];
  float m[S_SPLIT] = { m4.x, m4.y, m4.z, m4.w };
  float l[S_SPLIT] = { l4.x, l4.y, l4.z, l4.w };

  float M = fmaxf(fmaxf(m[0], m[1]), fmaxf(m[2], m[3]));
  float w[S_SPLIT]; float L = 0.f;
  #pragma unroll
  for (int s = 0; s < S_SPLIT; s++) { w[s] = ex2(m[s] - M); L += l[s] * w[s]; }
  float inv = 1.0f / L;

  float4 acc = make_float4(0.f, 0.f, 0.f, 0.f);
  #pragma unroll
  for (int s = 0; s < S_SPLIT; s++) {
    uint2 u = *(const uint2*)&g_po16[((size_t)s * ROWS + r) * 32 + pc];
    float a0, a1, a2, a3;
    f16unpack2(u.x, a0, a1);
    f16unpack2(u.y, a2, a3);
    acc.x += a0 * w[s]; acc.y += a1 * w[s];
    acc.z += a2 * w[s]; acc.w += a3 * w[s];
  }
  acc.x *= inv; acc.y *= inv; acc.z *= inv; acc.w *= inv;
  *(float4*)(out + (size_t)r * DD + pc * 2) = acc;
}

// ---------------------------------------------------------------------------
extern "C" void kernel_launch(void* const* d_in, const int* in_sizes, int n_in,
                              void* d_out, int out_size)
{
  const float* x  = (const float*)d_in[0];
  const float* Wk = (const float*)d_in[1];
  const float* Wq = (const float*)d_in[2];
  const float* Wv = (const float*)d_in[3];
  float* out = (float*)d_out;

  cudaFuncSetAttribute(proj_mma, cudaFuncAttributeMaxDynamicSharedMemorySize, SMEM_PROJ);
  cudaFuncSetAttribute(attn_mma, cudaFuncAttributeMaxDynamicSharedMemorySize, SMEM_ATT);

  prep_w<<<dim3(CC / 64, 3), 256>>>(Wk, Wq, Wv);
  proj_mma<<<ROWS / PM, 256, SMEM_PROJ>>>(x);
  attn_mma<<<dim3(TT / 128, BB, S_SPLIT), 256, SMEM_ATT>>>();
  combine_kernel<<<ROWS * 16 / 256, 256>>>(out);
}

// round 17
// speedup vs baseline: 1.4852x; 1.4852x over previous
#include <cuda_runtime.h>
#include <cuda_fp16.h>
#include <cstdint>

// Problem dims (fixed by reference)
#define BB 8
#define TT 2048
#define CC 1024
#define DD 64
#define ROWS (BB*TT)      // 16384
#define S_SPLIT 4
#define NEG_BIG  (-1.0e30f)
#define MASK_S   (-3.0e38f)
#define QSCALE   0.18033688f   // 0.125 * log2(e)

#define NTOT 192          // fused proj cols: 64 K | 64 Q | 64 V
#define KC 64             // K-chunk per pipeline stage (fp16 elems)
#define NCHUNK (CC/KC)    // 16

// proj smem: rows of 64 fp16 = 128B + 16B pad -> 144B pitch; 3-stage ring
#define PPITCH 144
#define PM 64                             // rows per proj CTA
#define XH_BYTES (PM*PPITCH)              // 9216
#define WH_BYTES (NTOT*PPITCH)            // 27648
#define STAGE_BYTES (XH_BYTES + WH_BYTES)     // 36864 (x single, w single)
#define SMEM_PROJ (3*STAGE_BYTES)             // 110592 -> 2 CTAs/SM

// attn smem: 3-stage KV ring (R15 config — measured best)
#define APITCH 144
#define Q_BYTES (128*APITCH)        // 18432 (Q single fp16)
#define KV_ARR  (64*APITCH)         // 9216
#define KV_STAGE (2*KV_ARR)         // 18432 (K, V single fp16)
#define SMEM_ATT (Q_BYTES + 3*KV_STAGE)   // 73728

// Scratch (allocation-free: __device__ globals)
__device__ uint32_t g_po16[S_SPLIT*ROWS*32];   // partial O as f16x2 pairs
__device__ float g_pm[S_SPLIT*ROWS];
__device__ float g_pl[S_SPLIT*ROWS];
__device__ __half g_wth[NTOT*CC];           // W^T fp16 single, [n][k]
__device__ __half g_qh[ROWS*DD];            // Q fp16 (pre-scaled QSCALE)
__device__ __half g_kh[ROWS*DD];            // K fp16
__device__ __half g_vh[ROWS*DD];            // V fp16 single

__device__ __forceinline__ void cpasync16u(uint32_t sa, const void* g){
  asm volatile("cp.async.cg.shared.global [%0], [%1], 16;\n" :: "r"(sa), "l"(g) : "memory");
}
__device__ __forceinline__ void cp_commit(){ asm volatile("cp.async.commit_group;\n" ::: "memory"); }
__device__ __forceinline__ void cp_wait1(){ asm volatile("cp.async.wait_group 1;\n" ::: "memory"); }
__device__ __forceinline__ void cp_wait2(){ asm volatile("cp.async.wait_group 2;\n" ::: "memory"); }

__device__ __forceinline__ uint32_t smem_u32(const void* p){
  return (uint32_t)__cvta_generic_to_shared(p);
}
__device__ __forceinline__ void ldm4(uint32_t* r, uint32_t addr){
  asm volatile("ldmatrix.sync.aligned.m8n8.x4.shared.b16 {%0,%1,%2,%3},[%4];"
    : "=r"(r[0]), "=r"(r[1]), "=r"(r[2]), "=r"(r[3]) : "r"(addr));
}
__device__ __forceinline__ void ldm4t(uint32_t* r, uint32_t addr){
  asm volatile("ldmatrix.sync.aligned.m8n8.x4.trans.shared.b16 {%0,%1,%2,%3},[%4];"
    : "=r"(r[0]), "=r"(r[1]), "=r"(r[2]), "=r"(r[3]) : "r"(addr));
}
// fp16 mma: m16n8k16, f32 accum
__device__ __forceinline__ void mma16816h(float* d, const uint32_t* a,
                                          uint32_t b0, uint32_t b1){
  asm volatile("mma.sync.aligned.m16n8k16.row.col.f32.f16.f16.f32 "
    "{%0,%1,%2,%3},{%4,%5,%6,%7},{%8,%9},{%0,%1,%2,%3};"
    : "+f"(d[0]), "+f"(d[1]), "+f"(d[2]), "+f"(d[3])
    : "r"(a[0]), "r"(a[1]), "r"(a[2]), "r"(a[3]), "r"(b0), "r"(b1));
}
// pack (a -> low half, b -> high half) as f16x2
__device__ __forceinline__ uint32_t f16pack2(float a, float b){
  uint32_t r; asm("cvt.rn.f16x2.f32 %0, %1, %2;" : "=r"(r) : "f"(b), "f"(a));
  return r;
}
__device__ __forceinline__ void f16unpack2(uint32_t u, float &a, float &b){
  asm("{ .reg .f16 l_, h_;\n\t mov.b32 {l_, h_}, %2;\n\t"
      "cvt.f32.f16 %0, l_;\n\t cvt.f32.f16 %1, h_;\n\t }"
      : "=f"(a), "=f"(b) : "r"(u));
}
// raw 2^x (MUFU.EX2)
__device__ __forceinline__ float ex2(float x){
  float y; asm("ex2.approx.f32 %0, %1;" : "=f"(y) : "f"(x)); return y;
}

// ---------------------------------------------------------------------------
// Kernel 0: W -> fp16 single, transposed [n][k], via smem tile (coalesced
// reads AND writes). grid = (CC/64, 3), 256 threads.
// ---------------------------------------------------------------------------
__global__ __launch_bounds__(256) void prep_w(
    const float* __restrict__ Wk, const float* __restrict__ Wq,
    const float* __restrict__ Wv)
{
  __shared__ float tile[64][65];
  const int kc = blockIdx.x;          // k-chunk of 64
  const int wy = blockIdx.y;          // which W
  const float* W = (wy == 0) ? Wk : ((wy == 1) ? Wq : Wv);
  const int tid = threadIdx.x;
  const int k0 = kc * 64;

  // load 64 k-rows x 64 cols, coalesced (col = fast index)
  #pragma unroll
  for (int i = 0; i < 16; i++) {
    int e = i * 256 + tid;            // 0..4095
    int k = e >> 6, c = e & 63;
    tile[k][c] = W[(size_t)(k0 + k) * DD + c];
  }
  __syncthreads();

  // write transposed: n-row gets 64 contiguous k values (as 32 u32 pairs)
  __half* outb = g_wth + (size_t)wy * 64 * CC;
  #pragma unroll
  for (int i = 0; i < 8; i++) {
    int e = i * 256 + tid;            // 0..2047
    int n = e >> 5, kp = (e & 31) * 2;
    uint32_t u = f16pack2(tile[kp][n], tile[kp + 1][n]);
    *(uint32_t*)(outb + (size_t)n * CC + k0 + kp) = u;
  }
}

// ---------------------------------------------------------------------------
// Kernel 1: QKV projection, fp16 1-term. grid = 256 CTAs x 64 rows,
// 256 thr (8 warps), warp tile 16x96, KC=64. 3-stage ring, W prefetch
// distance 2. Epilogue: Q (x QSCALE) / K / V all single fp16.
// (Byte-identical to R15.)
// ---------------------------------------------------------------------------
extern __shared__ char dsmem[];

__global__ __launch_bounds__(256, 2) void proj_mma(const float* __restrict__ x)
{
  const int tid  = threadIdx.x;
  const int wid  = tid >> 5;
  const int lane = tid & 31;
  const int rowBase = blockIdx.x * PM;

  const uint32_t sbase = smem_u32(dsmem);
  auto xB = [&](int st){ return sbase + (uint32_t)st * STAGE_BYTES; };
  auto wB = [&](int st){ return xB(st) + XH_BYTES; };

  const int wm = (wid & 3) * 16;       // 4 row groups x 16
  const int wn = (wid >> 2) * 96;      // 2 col groups x 96

  const uint32_t aOff = (uint32_t)((wm + (lane & 15)) * PPITCH + (lane >> 4) * 16);
  const int bN = wn + ((lane >> 4) & 1) * 8 + (lane & 7);
  const uint32_t bOff = (uint32_t)(bN * PPITCH + ((lane >> 3) & 1) * 16);

  float d[12][4];
  #pragma unroll
  for (int nf = 0; nf < 12; nf++)
    #pragma unroll
    for (int c = 0; c < 4; c++) d[nf][c] = 0.f;

  // x chunk: 64 rows x 64 cols fp32 = 1024 float4 -> 4/thread
  float4 xr[4];
  auto loadX = [&](int chunk) {
    const int k0 = chunk * KC;
    #pragma unroll
    for (int i = 0; i < 4; i++) {
      int f = i * 256 + tid;            // 0..1023
      int row = f >> 4, c4 = (f & 15) * 4;
      xr[i] = *(const float4*)(x + (size_t)(rowBase + row) * CC + k0 + c4);
    }
  };
  auto convertX = [&](int st) {
    const uint32_t xh = xB(st);
    #pragma unroll
    for (int i = 0; i < 4; i++) {
      int f = i * 256 + tid;
      int row = f >> 4;
      uint32_t boff = (uint32_t)(row * PPITCH + (f & 15) * 8);
      float4 v = xr[i];
      uint32_t h01 = f16pack2(v.x, v.y);
      uint32_t h23 = f16pack2(v.z, v.w);
      asm volatile("st.shared.v2.b32 [%0], {%1,%2};" :: "r"(xh + boff), "r"(h01), "r"(h23) : "memory");
    }
  };
  // issueW always commits (empty group when !valid) to keep group counting
  // uniform for wait_group N.
  auto issueW = [&](int chunk, bool valid) {
    if (valid) {
      const int k0 = chunk * KC;
      const uint32_t wb = wB(chunk % 3);
      #pragma unroll
      for (int i = 0; i < 6; i++) {
        int gid = i * 256 + tid;             // 0..1535
        int n = gid >> 3, c = gid & 7;
        cpasync16u(wb + (uint32_t)(n * PPITCH + c * 16),
                   g_wth + (size_t)n * CC + k0 + c * 8);
      }
    }
    cp_commit();
  };

  // ---- prologue: W groups for chunks 0,1; x0 converted; x1 in regs ----
  loadX(0);
  issueW(0, true);
  convertX(0);
  loadX(1);
  issueW(1, true);

  for (int it = 0; it < NCHUNK; it++) {
    const int cur = it % 3;
    cp_wait1();                    // W(it) ready (issued 2 iterations back)
    __syncthreads();
    issueW(it + 2, it + 2 < NCHUNK);

    #pragma unroll
    for (int ks = 0; ks < 4; ks++) {
      uint32_t ah[4];
      ldm4(ah, xB(cur) + aOff + (uint32_t)(ks * 32));
      #pragma unroll
      for (int nf2 = 0; nf2 < 6; nf2++) {
        uint32_t bw[4];
        ldm4(bw, wB(cur) + bOff + (uint32_t)(nf2 * 16 * PPITCH + ks * 32));
        mma16816h(d[2 * nf2],     ah, bw[0], bw[1]);
        mma16816h(d[2 * nf2 + 1], ah, bw[2], bw[3]);
      }
    }

    if (it + 1 < NCHUNK) convertX((it + 1) % 3);  // xr holds chunk it+1
    if (it + 2 < NCHUNK) loadX(it + 2);
  }

  // epilogue: Q single (x QSCALE), K single, V single
  const int erow = lane >> 2;
  const int ecol = (lane & 3) * 2;
  #pragma unroll
  for (int nf = 0; nf < 12; nf++) {
    int n0 = wn + nf * 8;
    int part = n0 >> 6;
    __half* hp = (part == 0) ? g_kh : ((part == 1) ? g_qh : g_vh);
    float sc = (part == 1) ? QSCALE : 1.0f;
    int col = (n0 & 63) + ecol;
    size_t r0 = (size_t)(rowBase + wm + erow);
    size_t r1 = r0 + 8;
    *(uint32_t*)(hp + r0 * DD + col) = f16pack2(d[nf][0] * sc, d[nf][1] * sc);
    *(uint32_t*)(hp + r1 * DD + col) = f16pack2(d[nf][2] * sc, d[nf][3] * sc);
  }
}

// ---------------------------------------------------------------------------
// Kernel 2: FlashAttention-2 on fp16 mma.sync. 256 thr, 8 warps (m16 each),
// 128-query blocks, heavy-first. 3-stage KV ring, prefetch distance 2.
// Softmax in base-2 (ex2.approx). Partial O stored f16x2.
// (Byte-identical to R15 — the measured-best attention.)
// ---------------------------------------------------------------------------
__global__ __launch_bounds__(256, 2) void attn_mma()
{
  const int qb  = (TT / 128 - 1) - blockIdx.x;   // heavy-first
  const int b   = blockIdx.y;
  const int sp  = blockIdx.z;
  const int tid = threadIdx.x;
  const int wid = tid >> 5;
  const int lane = tid & 31;

  const int ntt = 2 * (qb + 1);        // total 64-key tiles for this q-block
  const int nt  = (ntt > sp) ? (ntt - sp + 3) / 4 : 0;

  float o[8][4];
  #pragma unroll
  for (int nf = 0; nf < 8; nf++)
    #pragma unroll
    for (int c = 0; c < 4; c++) o[nf][c] = 0.f;
  float m0 = NEG_BIG, m1 = NEG_BIG, l0 = 0.f, l1 = 0.f;

  const int erow = lane >> 2;
  const int ecol = (lane & 3) * 2;
  const int row0g = b * TT + qb * 128 + wid * 16 + erow;

  if (nt == 0) goto epilogue;

  {
    const uint32_t sb  = smem_u32(dsmem);
    const uint32_t QS  = sb;
    const uint32_t KVB = sb + Q_BYTES;

    auto issueKV = [&](int tix, bool valid) {
      if (valid) {
        const int k0 = (sp + tix * 4) * 64;
        const uint32_t base = KVB + (uint32_t)(tix % 3) * KV_STAGE;
        #pragma unroll
        for (int i = 0; i < 4; i++) {
          int gid = i * 256 + tid;               // 0..1023
          int arr = gid >> 9;                    // 0=K,1=V
          int g2 = gid & 511;
          int row = g2 >> 3, ch = g2 & 7;
          const __half* ap = (arr == 0) ? g_kh : g_vh;
          cpasync16u(base + (uint32_t)(arr * KV_ARR + row * APITCH + ch * 16),
                     ap + (size_t)(b * TT + k0 + row) * DD + ch * 8);
        }
      }
      cp_commit();
    };

    // ---- stage Q (group 0) + first two KV tiles (groups 1,2) ----
    {
      const int rbase = b * TT + qb * 128;
      #pragma unroll
      for (int i = 0; i < 4; i++) {
        int gid = i * 256 + tid;               // 0..1023
        int row = gid >> 3, ch = gid & 7;
        cpasync16u(QS + (uint32_t)(row * APITCH + ch * 16),
                   g_qh + (size_t)(rbase + row) * DD + ch * 8);
      }
      cp_commit();
    }
    issueKV(0, true);
    issueKV(1, 1 < nt);

    cp_wait2();              // Q done (2 KV groups may remain outstanding)
    __syncthreads();

    // ---- Q fragments (register-resident, single) ----
    const uint32_t qoff = (uint32_t)((wid * 16 + (lane & 15)) * APITCH + (lane >> 4) * 16);
    uint32_t qh[4][4];
    #pragma unroll
    for (int ks = 0; ks < 4; ks++) ldm4(qh[ks], QS + qoff + ks * 32);

    const uint32_t koff = (uint32_t)((((lane >> 4) & 1) * 8 + (lane & 7)) * APITCH + ((lane >> 3) & 1) * 16);
    const uint32_t voff = (uint32_t)((((lane >> 3) & 1) * 8 + (lane & 7)) * APITCH + ((lane >> 4) & 1) * 16);

    for (int tix = 0; tix < nt; tix++) {
      const int k0 = (sp + tix * 4) * 64;
      cp_wait1();            // tile tix ready (issued 2 iterations ago)
      __syncthreads();
      issueKV(tix + 2, tix + 2 < nt);

      const uint32_t stage = KVB + (uint32_t)(tix % 3) * KV_STAGE;
      const uint32_t KH = stage;
      const uint32_t VH = stage + KV_ARR;

      // ---- S = Q K^T (1 term) ----
      float s[8][4];
      #pragma unroll
      for (int nf = 0; nf < 8; nf++)
        #pragma unroll
        for (int c = 0; c < 4; c++) s[nf][c] = 0.f;

      #pragma unroll
      for (int ks = 0; ks < 4; ks++) {
        #pragma unroll
        for (int g = 0; g < 4; g++) {
          uint32_t bh[4];
          ldm4(bh, KH + koff + (uint32_t)(g * 16 * APITCH + ks * 32));
          mma16816h(s[2*g],   qh[ks], bh[0], bh[1]);
          mma16816h(s[2*g+1], qh[ks], bh[2], bh[3]);
        }
      }

      // ---- causal mask (diagonal tiles only) ----
      if (k0 + 63 > qb * 128) {
        const int rlo = qb * 128 + wid * 16 + erow;
        #pragma unroll
        for (int nf = 0; nf < 8; nf++) {
          int key = k0 + nf * 8 + ecol;
          if (key     > rlo)     s[nf][0] = MASK_S;
          if (key + 1 > rlo)     s[nf][1] = MASK_S;
          if (key     > rlo + 8) s[nf][2] = MASK_S;
          if (key + 1 > rlo + 8) s[nf][3] = MASK_S;
        }
      }

      // ---- online softmax, base-2 (rows: l/4 and l/4+8) ----
      float r0 = fmaxf(s[0][0], s[0][1]);
      float r1 = fmaxf(s[0][2], s[0][3]);
      #pragma unroll
      for (int nf = 1; nf < 8; nf++) {
        r0 = fmaxf(r0, fmaxf(s[nf][0], s[nf][1]));
        r1 = fmaxf(r1, fmaxf(s[nf][2], s[nf][3]));
      }
      r0 = fmaxf(r0, __shfl_xor_sync(0xffffffffu, r0, 1));
      r0 = fmaxf(r0, __shfl_xor_sync(0xffffffffu, r0, 2));
      r1 = fmaxf(r1, __shfl_xor_sync(0xffffffffu, r1, 1));
      r1 = fmaxf(r1, __shfl_xor_sync(0xffffffffu, r1, 2));
      float mn0 = fmaxf(m0, r0), mn1 = fmaxf(m1, r1);
      float cr0 = ex2(m0 - mn0), cr1 = ex2(m1 - mn1);
      l0 *= cr0; l1 *= cr1; m0 = mn0; m1 = mn1;
      #pragma unroll
      for (int nf = 0; nf < 8; nf++) {
        o[nf][0] *= cr0; o[nf][1] *= cr0;
        o[nf][2] *= cr1; o[nf][3] *= cr1;
      }

      // ---- ex2, row sums, P -> A-frag fp16 single ----
      float sum0 = 0.f, sum1 = 0.f;
      uint32_t ph[4][4];
      #pragma unroll
      for (int nf = 0; nf < 8; nf++) {
        float p0 = ex2(s[nf][0] - m0);
        float p1 = ex2(s[nf][1] - m0);
        float p2 = ex2(s[nf][2] - m1);
        float p3 = ex2(s[nf][3] - m1);
        sum0 += p0 + p1; sum1 += p2 + p3;
        int kk = nf >> 1, bs = (nf & 1) * 2;
        ph[kk][bs]     = f16pack2(p0, p1);
        ph[kk][bs + 1] = f16pack2(p2, p3);
      }
      sum0 += __shfl_xor_sync(0xffffffffu, sum0, 1);
      sum0 += __shfl_xor_sync(0xffffffffu, sum0, 2);
      sum1 += __shfl_xor_sync(0xffffffffu, sum1, 1);
      sum1 += __shfl_xor_sync(0xffffffffu, sum1, 2);
      l0 += sum0; l1 += sum1;

      // ---- O += P V (1 term; V via trans-ldmatrix) ----
      #pragma unroll
      for (int kk = 0; kk < 4; kk++) {
        #pragma unroll
        for (int dg = 0; dg < 4; dg++) {
          uint32_t vh[4];
          ldm4t(vh, VH + voff + (uint32_t)(kk * 16 * APITCH + dg * 32));
          mma16816h(o[2*dg],   ph[kk], vh[0], vh[1]);
          mma16816h(o[2*dg+1], ph[kk], vh[2], vh[3]);
        }
      }
    }
  }

epilogue:
  {
    size_t pr0 = (size_t)sp * ROWS + row0g;
    size_t pr1 = pr0 + 8;
    if ((lane & 3) == 0) {
      g_pm[pr0] = m0; g_pl[pr0] = l0;
      g_pm[pr1] = m1; g_pl[pr1] = l1;
    }
    const int pcol = (lane & 3);
    #pragma unroll
    for (int nf = 0; nf < 8; nf++) {
      g_po16[pr0 * 32 + nf * 4 + pcol] = f16pack2(o[nf][0], o[nf][1]);
      g_po16[pr1 * 32 + nf * 4 + pcol] = f16pack2(o[nf][2], o[nf][3]);
    }
  }
}

// ---------------------------------------------------------------------------
// Kernel 3: LSE combine (base-2 weights). One thread per output float4,
// grid = 1024 x 256. (Byte-identical to R15.)
// ---------------------------------------------------------------------------
__global__ __launch_bounds__(256) void combine_kernel(float* __restrict__ out)
{
  int gid = blockIdx.x * 256 + threadIdx.x;   // 0 .. ROWS*16-1
  int r  = gid >> 4;
  int pc = (gid & 15) * 2;                    // f16x2-pair index (0..30)

  float m[S_SPLIT], l[S_SPLIT];
  #pragma unroll
  for (int s = 0; s < S_SPLIT; s++) {
    m[s] = g_pm[(size_t)s * ROWS + r];
    l[s] = g_pl[(size_t)s * ROWS + r];
  }
  float M = fmaxf(fmaxf(m[0], m[1]), fmaxf(m[2], m[3]));
  float w[S_SPLIT]; float L = 0.f;
  #pragma unroll
  for (int s = 0; s < S_SPLIT; s++) { w[s] = ex2(m[s] - M); L += l[s] * w[s]; }
  float inv = 1.0f / L;

  float4 acc = make_float4(0.f, 0.f, 0.f, 0.f);
  #pragma unroll
  for (int s = 0; s < S_SPLIT; s++) {
    uint2 u = *(const uint2*)&g_po16[((size_t)s * ROWS + r) * 32 + pc];
    float a0, a1, a2, a3;
    f16unpack2(u.x, a0, a1);
    f16unpack2(u.y, a2, a3);
    acc.x += a0 * w[s]; acc.y += a1 * w[s];
    acc.z += a2 * w[s]; acc.w += a3 * w[s];
  }
  acc.x *= inv; acc.y *= inv; acc.z *= inv; acc.w *= inv;
  *(float4*)(out + (size_t)r * DD + pc * 2) = acc;
}

// ---------------------------------------------------------------------------
extern "C" void kernel_launch(void* const* d_in, const int* in_sizes, int n_in,
                              void* d_out, int out_size)
{
  const float* x  = (const float*)d_in[0];
  const float* Wk = (const float*)d_in[1];
  const float* Wq = (const float*)d_in[2];
  const float* Wv = (const float*)d_in[3];
  float* out = (float*)d_out;

  cudaFuncSetAttribute(proj_mma, cudaFuncAttributeMaxDynamicSharedMemorySize, SMEM_PROJ);
  cudaFuncSetAttribute(attn_mma, cudaFuncAttributeMaxDynamicSharedMemorySize, SMEM_ATT);

  prep_w<<<dim3(CC / 64, 3), 256>>>(Wk, Wq, Wv);
  proj_mma<<<ROWS / PM, 256, SMEM_PROJ>>>(x);
  attn_mma<<<dim3(TT / 128, BB, S_SPLIT), 256, SMEM_ATT>>>();
  combine_kernel<<<ROWS * 16 / 256, 256>>>(out);
}